// round 15
// baseline (speedup 1.0000x reference)
#include <cuda_runtime.h>
#include <math.h>

// QSP expectation Re(<0|U|0>) = f(cos x); f even parity, degree 54 in c
// => f = sum_{j=0}^{27} d_j T_j(y), y = cos(2x)
// => f(y) = G(u) + y*H(u), u = 2y^2-1 = cos(4x),
//    g_m = d_{2m};  h_0 = sum_m (-1)^m d_{2m+1}, h_k = 2 sum_{m>=k} (-1)^(m-k) d_{2m+1}.
// Fused single kernel, 512x512, 2 elems/thread (occ ~71%).
// KEY CHANGE (R15): per-element cosine moved OFF the MUFU pipe (which was the
// invariant ~7100-cycle/SMSP bottleneck: 524288 __cosf x rt8) onto the mostly
// idle FMA pipe: magic-number range reduction + degree-10 even Taylor,
// err < 5e-7. MUFU remains only in the tiny prologue.

#define NSTEPS 54
#define NPH    55
#define NNODE  28
#define NCHUNK 9
#define CSTEP  6
#define NHALF  14
#define TPB    512

#define SU2_COMPOSE(a_r,a_i,b_r,b_i, alr,ali,ber,bei) do {                   \
    float nar = a_r*alr - a_i*ali - b_r*ber - b_i*bei;                       \
    float nai = a_r*ali + a_i*alr + b_r*bei - b_i*ber;                       \
    float nbr = a_r*ber - a_i*bei + b_r*alr + b_i*ali;                       \
    float nbi = a_r*bei + a_i*ber + b_i*alr - b_r*ali;                       \
    a_r = nar; a_i = nai; b_r = nbr; b_i = nbi;                              \
} while (0)

// cos(t) for |t| <~ 100, abs err < 5e-7. FMA/ALU pipes only (no MUFU).
// n = rint(t/pi) via magic-number add; r = t - n*pi (2-step); (-1)^n by
// sign-bit XOR from the parity bit of the magic mantissa; Taylor deg-10.
__device__ __forceinline__ float fcos_fma(float t) {
    const float MAGIC = 12582912.0f;             // 1.5 * 2^23
    float k = fmaf(t, 0.318309886f, MAGIC);      // t/pi + magic
    int   ki = __float_as_int(k);
    float n = k - MAGIC;                          // rint(t/pi)
    float r = fmaf(n, -3.14159274f, t);           // t - n*pi_hi
    r = fmaf(n, 8.74227766e-8f, r);               // - n*pi_lo  (pi_lo<0)
    float r2 = r * r;
    float c = -2.75573192e-7f;
    c = fmaf(c, r2, 2.48015873e-5f);
    c = fmaf(c, r2, -1.38888889e-3f);
    c = fmaf(c, r2, 4.16666667e-2f);
    c = fmaf(c, r2, -0.5f);
    c = fmaf(c, r2, 1.0f);
    return __int_as_float(__float_as_int(c) ^ ((ki & 1) << 31));
}

__global__ void __launch_bounds__(TPB, 4) qsp_fused(
    const float2* __restrict__ x2,
    const float*  __restrict__ p,
    const float2* __restrict__ a2,
    const float*  __restrict__ bias,
    float2* __restrict__ out2)
{
    __shared__ float  ph[NPH];
    __shared__ float4 chunk[NNODE * NCHUNK];
    __shared__ float  fsh[NNODE];
    __shared__ float  psum[NNODE * 4];
    __shared__ float  dsh[NNODE];
    __shared__ float2 ghsh[NHALF];                // (g_k, h_k) interleaved
    const float PI = 3.14159265358979323846f;
    int tid = threadIdx.x;
    int i = blockIdx.x * TPB + tid;               // grid sized exactly

    // Prefetch element data immediately: LDGs in flight through the prologue.
    float2 xv, av;
    float b0;
    {
        const float2* xp = x2 + i;
        const float2* ap = a2 + i;
        asm volatile("ld.global.nc.v2.f32 {%0,%1}, [%2];"
                     : "=f"(xv.x), "=f"(xv.y) : "l"(xp));
        asm volatile("ld.global.nc.v2.f32 {%0,%1}, [%2];"
                     : "=f"(av.x), "=f"(av.y) : "l"(ap));
        asm volatile("ld.global.nc.f32 %0, [%1];" : "=f"(b0) : "l"(bias));
    }

    if (tid < NPH) ph[tid] = p[tid];
    __syncthreads();

    // Phase 1: 252 threads, each a 6-step SU(2) partial product at node m.
    if (tid < NNODE * NCHUNK) {
        int m = tid / NCHUNK;
        int j = tid % NCHUNK;
        float th = PI * ((float)m + 0.5f) / 56.0f;   // y_m = cos(2*th)
        float cm, sm;
        __sincosf(th, &sm, &cm);
        float myph[CSTEP];
        #pragma unroll
        for (int s = 0; s < CSTEP; s++) myph[s] = ph[1 + j * CSTEP + s];
        float er, ei;
        __sincosf(myph[0], &ei, &er);
        float a_r = cm * er, a_i = cm * ei;          // C = M_first
        float b_r = sm * ei, b_i = sm * er;
        #pragma unroll
        for (int s = 1; s < CSTEP; s++) {
            __sincosf(myph[s], &ei, &er);
            float alr = cm * er, ali = cm * ei;      // alpha = c*e
            float ber = sm * ei, bei = sm * er;      // beta  = i*s*conj(e)
            SU2_COMPOSE(a_r, a_i, b_r, b_i, alr, ali, ber, bei);
        }
        chunk[tid] = make_float4(a_r, a_i, b_r, b_i);
    }
    __syncthreads();

    // Phase 2: per-node ordered composition of 9 chunks.
    if (tid < NNODE) {
        float4 Mv[NCHUNK];
        #pragma unroll
        for (int j = 0; j < NCHUNK; j++) Mv[j] = chunk[tid * NCHUNK + j];
        float a_r = Mv[0].x, a_i = Mv[0].y, b_r = Mv[0].z, b_i = Mv[0].w;
        #pragma unroll
        for (int j = 1; j < NCHUNK; j++)
            SU2_COMPOSE(a_r, a_i, b_r, b_i, Mv[j].x, Mv[j].y, Mv[j].z, Mv[j].w);
        float c0, s0;
        __sincosf(ph[0], &s0, &c0);
        fsh[tid] = c0 * a_r - s0 * a_i;              // f(theta_m)
    }
    __syncthreads();

    // Phase 3a: 28-pt DCT over 112 threads (4 partials of 7 terms per j).
    // Exact integer angle reduction: cos(pi*r/56) = -cos(pi*r/56 - pi), r mod 112.
    if (tid < NNODE * 4) {
        int j = tid >> 2;
        int q = tid & 3;
        float s = 0.f;
        int m0 = q * 7;
        #pragma unroll
        for (int m = m0; m < m0 + 7; m++) {
            int r = (j * (2 * m + 1)) % 112;
            float ang = (PI / 56.0f) * (float)r - PI;
            s = fmaf(fsh[m], -__cosf(ang), s);
        }
        psum[tid] = s;
    }
    __syncthreads();

    // Phase 3b: reduce partials -> d_j.
    if (tid < NNODE) {
        float s = ((psum[tid * 4] + psum[tid * 4 + 1]) +
                   (psum[tid * 4 + 2] + psum[tid * 4 + 3])) * (2.0f / (float)NNODE);
        if (tid == 0) s *= 0.5f;
        dsh[tid] = s;
    }
    __syncthreads();

    // Phase 4: even/odd split (exact integer weights), interleaved (g,h).
    if (tid < NHALF) {
        float g = dsh[2 * tid];
        float h = 0.f, sign = 1.f;
        #pragma unroll
        for (int m = 0; m < NHALF; m++) {
            if (m >= tid) {
                h = fmaf(sign, dsh[2 * m + 1], h);
                sign = -sign;
            }
        }
        if (tid > 0) h *= 2.0f;
        ghsh[tid] = make_float2(g, h);
    }
    __syncthreads();

    // Eval: 2 elements/thread, FMA-pipe cosine, 4 independent 13-step chains.
    float y0 = fcos_fma(xv.x + xv.x);
    float y1 = fcos_fma(xv.y + xv.y);
    float u0 = fmaf(2.0f * y0, y0, -1.0f);           // u = 2y^2 - 1
    float u1 = fmaf(2.0f * y1, y1, -1.0f);
    float tu0 = 2.0f * u0, tu1 = 2.0f * u1;

    float gb1_0 = 0.f, gb2_0 = 0.f, hb1_0 = 0.f, hb2_0 = 0.f;
    float gb1_1 = 0.f, gb2_1 = 0.f, hb1_1 = 0.f, hb2_1 = 0.f;

    #pragma unroll
    for (int k = NHALF - 1; k >= 1; k--) {
        float2 gh = ghsh[k];                          // one LDS.64 broadcast
        float ng0 = fmaf(tu0, gb1_0, gh.x - gb2_0);
        float nh0 = fmaf(tu0, hb1_0, gh.y - hb2_0);
        float ng1 = fmaf(tu1, gb1_1, gh.x - gb2_1);
        float nh1 = fmaf(tu1, hb1_1, gh.y - hb2_1);
        gb2_0 = gb1_0; gb1_0 = ng0;  hb2_0 = hb1_0; hb1_0 = nh0;
        gb2_1 = gb1_1; gb1_1 = ng1;  hb2_1 = hb1_1; hb1_1 = nh1;
    }

    float2 gh0 = ghsh[0];
    float G0 = fmaf(u0, gb1_0, gh0.x - gb2_0);
    float H0 = fmaf(u0, hb1_0, gh0.y - hb2_0);
    float G1 = fmaf(u1, gb1_1, gh0.x - gb2_1);
    float H1 = fmaf(u1, hb1_1, gh0.y - hb2_1);

    float f0 = fmaf(y0, H0, G0);                      // f = G + y*H
    float f1 = fmaf(y1, H1, G1);

    float2 o;
    o.x = fmaf(av.x, f0, b0);
    o.y = fmaf(av.y, f1, b0);
    out2[i] = o;
}

extern "C" void kernel_launch(void* const* d_in, const int* in_sizes, int n_in,
                              void* d_out, int out_size) {
    const float* x    = (const float*)d_in[0];
    const float* p    = (const float*)d_in[1];
    const float* al   = (const float*)d_in[2];
    const float* bias = (const float*)d_in[3];

    int n2 = out_size / 2;                            // 262144 threads
    int blocks = n2 / TPB;                            // 512 blocks x 512 threads
    qsp_fused<<<blocks, TPB>>>((const float2*)x, p, (const float2*)al, bias,
                               (float2*)d_out);
}